// round 8
// baseline (speedup 1.0000x reference)
#include <cuda_runtime.h>
#include <cuda_fp16.h>

#define DD 160
#define HH 160
#define WW 160
#define NB 2
#define HW_ (HH * WW)
#define HW2 (HW_ / 2)
#define DHW_ (DD * HH * WW)          // 4,096,000
#define DHW2 (DHW_ / 2)
#define NVOX (NB * DHW_)             // 8,192,000
#define DCH 4
#define DL  (DD / DCH)               // 40
#define HCH 5
#define HL  (HH / HCH)               // 32
#define NWD (80 * DCH * HH * NB)     // 102,400 passWD threads
#define NPART 500                    // passH blocks

#define G0c 0.0125602f
#define G1c 0.0788279f
#define G2c 0.2372961f
#define G3c 0.3426315f

typedef unsigned long long u64;

__device__ __forceinline__ u64 pk(float lo, float hi) {
    u64 r; asm("mov.b64 %0, {%1, %2};" : "=l"(r) : "f"(lo), "f"(hi)); return r;
}
__device__ __forceinline__ float2 upk(u64 v) {
    float2 r; asm("mov.b64 {%0, %1}, %2;" : "=f"(r.x), "=f"(r.y) : "l"(v)); return r;
}
__device__ __forceinline__ u64 fma2(u64 a, u64 b, u64 c) {
    u64 d; asm("fma.rn.f32x2 %0, %1, %2, %3;" : "=l"(d) : "l"(a), "l"(b), "l"(c)); return d;
}
__device__ __forceinline__ u64 mul2(u64 a, u64 b) {
    u64 d; asm("mul.rn.f32x2 %0, %1, %2;" : "=l"(d) : "l"(a), "l"(b)); return d;
}
__device__ __forceinline__ u64 add2(u64 a, u64 b) {
    u64 d; asm("add.rn.f32x2 %0, %1, %2;" : "=l"(d) : "l"(a), "l"(b)); return d;
}
__device__ __forceinline__ u64 h2f2(__half2 h) {
    float2 f = __half22float2(h); return pk(f.x, f.y);
}

// zero-padding valid-weight factor per axis
__device__ __forceinline__ float bfac(int i) {
    float f = 1.f;
    if (i < 3)   f -= (i == 2 ? G0c : (i == 1 ? (G0c + G1c) : (G0c + G1c + G2c)));
    if (i > 156) f -= (i == 157 ? G0c : (i == 158 ? (G0c + G1c) : (G0c + G1c + G2c)));
    return f;
}

// fp16 scratch: 5 shifted conv-wd fields x 2 batches (81.92 MB)
__device__ __half g_buf2[10u * DHW_];
__device__ float g_partials[NPART];
__device__ int g_ctr;

struct F5 { u64 a[5]; };

// W-conv of the 5 shifted fields for one w-pair of one row.
// pr/tr point at (row, w2). Masks m/mh zero out-of-range taps AND apply the
// -0.5 shift in one FFMA: qa = v*m - 0.5*m.
__device__ __forceinline__ F5 wconv_row(const float* __restrict__ pr,
                                        const float* __restrict__ tr,
                                        const float* m, const float* mh,
                                        int wp) {
    const float2 z2 = {0.f, 0.f};
    float v[10], u[10];
    float2 x;
    x = (wp >= 2)  ? *(const float2*)(pr - 4) : z2; v[0] = x.x; v[1] = x.y;
    x = (wp >= 1)  ? *(const float2*)(pr - 2) : z2; v[2] = x.x; v[3] = x.y;
    x = *(const float2*)(pr);                        v[4] = x.x; v[5] = x.y;
    x = *(const float2*)(pr + 2);                    v[6] = x.x; v[7] = x.y;
    x = (wp <= 77) ? *(const float2*)(pr + 4) : z2;  v[8] = x.x; v[9] = x.y;
    x = (wp >= 2)  ? *(const float2*)(tr - 4) : z2;  u[0] = x.x; u[1] = x.y;
    x = (wp >= 1)  ? *(const float2*)(tr - 2) : z2;  u[2] = x.x; u[3] = x.y;
    x = *(const float2*)(tr);                        u[4] = x.x; u[5] = x.y;
    x = *(const float2*)(tr + 2);                    u[6] = x.x; u[7] = x.y;
    x = (wp <= 77) ? *(const float2*)(tr + 4) : z2;  u[8] = x.x; u[9] = x.y;

    float qa[8], ra[8];
#pragma unroll
    for (int i = 0; i < 8; ++i) {
        qa[i] = fmaf(v[i + 1], m[i], mh[i]);
        ra[i] = fmaf(u[i + 1], m[i], mh[i]);
    }
    u64 P[7], R[7];
#pragma unroll
    for (int k = 0; k < 7; ++k) {
        P[k] = pk(qa[k], qa[k + 1]);
        R[k] = pk(ra[k], ra[k + 1]);
    }
    const float gs[7] = {G0c, G1c, G2c, G3c, G2c, G1c, G0c};
    F5 o;
    {
        u64 g = pk(gs[0], gs[0]);
        o.a[0] = mul2(g, P[0]);
        o.a[1] = mul2(g, R[0]);
        o.a[2] = mul2(g, mul2(P[0], P[0]));
        o.a[3] = mul2(g, mul2(R[0], R[0]));
        o.a[4] = mul2(g, mul2(P[0], R[0]));
    }
#pragma unroll
    for (int k = 1; k < 7; ++k) {
        u64 g = pk(gs[k], gs[k]);
        o.a[0] = fma2(g, P[k], o.a[0]);
        o.a[1] = fma2(g, R[k], o.a[1]);
        o.a[2] = fma2(g, mul2(P[k], P[k]), o.a[2]);
        o.a[3] = fma2(g, mul2(R[k], R[k]), o.a[3]);
        o.a[4] = fma2(g, mul2(P[k], R[k]), o.a[4]);
    }
    return o;
}

// ---------------------------------------------------------------------------
// passWD: fused W-conv + D-conv. Thread = (n, h, w-pair, d-chunk); walks d,
// W-conv per row in registers, rolling 5x7 packed d-window, fp16 stores.
// ---------------------------------------------------------------------------
__global__ void __launch_bounds__(256) passWD(const float* __restrict__ p,
                                              const float* __restrict__ t) {
    int tid = blockIdx.x * blockDim.x + threadIdx.x;
    if (tid >= NWD) return;          // 102,400 workers
    int wp  = tid % 80;
    int rem = tid / 80;
    int ci  = rem % DCH;
    int rm2 = rem / DCH;
    int h   = rm2 % HH;
    int n   = rm2 / HH;
    int d0  = ci * DL;
    int w2  = 2 * wp;

    // tap masks: tap i covers w = w2-3+i, i=0..7
    float m[8], mh[8];
#pragma unroll
    for (int i = 0; i < 8; ++i) {
        int w = w2 - 3 + i;
        m[i]  = (w >= 0 && w < WW) ? 1.f : 0.f;
        mh[i] = -0.5f * m[i];
    }

    const float* pp = p + (long)n * DHW_ + (long)h * WW + w2;
    const float* tt = t + (long)n * DHW_ + (long)h * WW + w2;

    u64 win[5][7];
#pragma unroll
    for (int k = 0; k < 7; ++k) {
        int dd = d0 - 3 + k;
        if (dd >= 0 && dd < DD) {
            F5 f = wconv_row(pp + (long)dd * HW_, tt + (long)dd * HW_, m, mh, wp);
#pragma unroll
            for (int ff = 0; ff < 5; ++ff) win[ff][k] = f.a[ff];
        } else {
#pragma unroll
            for (int ff = 0; ff < 5; ++ff) win[ff][k] = 0;
        }
    }

    const u64 G0p = pk(G0c,G0c), G1p = pk(G1c,G1c), G2p = pk(G2c,G2c), G3p = pk(G3c,G3c);
    const float* pc = pp + (long)(d0 + 4) * HW_;
    const float* tc = tt + (long)(d0 + 4) * HW_;
    __half2* dst = (__half2*)g_buf2 + (long)n * DHW2 + (long)d0 * HW2 + (long)h * 80 + wp;

#pragma unroll 1
    for (int i = 0; i < DL; ++i) {
        // feed row dn = d0+i+4 (issue loads early; W-conv math overlaps D-conv)
        int dn = d0 + i + 4;
        F5 nf;
        if (dn < DD) {
            nf = wconv_row(pc, tc, m, mh, wp);
        } else {
#pragma unroll
            for (int ff = 0; ff < 5; ++ff) nf.a[ff] = 0;
        }

        // D-conv from window -> fp16 store
#pragma unroll
        for (int f = 0; f < 5; ++f) {
            u64 y = mul2(G0p, win[f][0]);
            y = fma2(G1p, win[f][1], y);
            y = fma2(G2p, win[f][2], y);
            y = fma2(G3p, win[f][3], y);
            y = fma2(G2p, win[f][4], y);
            y = fma2(G1p, win[f][5], y);
            y = fma2(G0p, win[f][6], y);
            float2 yf = upk(y);
            dst[(long)(f * NB) * DHW2] = __floats2half2_rn(yf.x, yf.y);
        }

        // shift windows, insert new row
#pragma unroll
        for (int f = 0; f < 5; ++f) {
#pragma unroll
            for (int k = 0; k < 6; ++k) win[f][k] = win[f][k + 1];
            win[f][6] = nf.a[f];
        }
        pc += HW_; tc += HW_; dst += HW2;
    }
}

// ---------------------------------------------------------------------------
// passH: streaming 7-tap H-conv of 5 fields + exact border reconstruction +
// SSIM + per-thread accumulation + block reduction + last-block final reduce.
// Thread = (n, d, w-pair, h-chunk of 32).
// ---------------------------------------------------------------------------
__global__ void __launch_bounds__(256) passH(float* __restrict__ out) {
    int tid = blockIdx.x * blockDim.x + threadIdx.x;   // 128,000 exactly
    int wp  = tid % 80;
    int rem = tid / 80;
    int ci  = rem % HCH;
    int rm2 = rem / HCH;
    int d   = rm2 % DD;
    int n   = rm2 / DD;
    int h0  = ci * HL;
    int w2  = 2 * wp;

    const u64 G0p = pk(G0c,G0c), G1p = pk(G1c,G1c), G2p = pk(G2c,G2c), G3p = pk(G3c,G3c);
    const u64 K05 = pk(0.5f,0.5f), Kn025 = pk(-0.25f,-0.25f), K2 = pk(2.f,2.f);
    const u64 KC1 = pk(1e-4f,1e-4f), KC2 = pk(9e-4f,9e-4f), Kn1 = pk(-1.f,-1.f);

    float bd = bfac(d);
    u64 wwp = pk(bd * bfac(w2), bd * bfac(w2 + 1));

    const __half2* base[5];
#pragma unroll
    for (int f = 0; f < 5; ++f)
        base[f] = (const __half2*)g_buf2 + (long)(f * NB + n) * DHW2 +
                  (long)d * HW2 + wp;

    u64 win[5][7];
#pragma unroll
    for (int k = 0; k < 7; ++k) {
        int row = h0 - 3 + k;
        bool v = (row >= 0) && (row < HH);
        int ro = (v ? row : 0) * 80;
#pragma unroll
        for (int f = 0; f < 5; ++f)
            win[f][k] = v ? h2f2(base[f][ro]) : 0;
    }

    float acc_ssim = 0.f;
    int po = (h0 + 4) * 80;

#pragma unroll 4
    for (int i = 0; i < HL; ++i) {
        int h = h0 + i;
        int hn = h + 4;
        bool v = (hn < HH);
        u64 nxt[5];
#pragma unroll
        for (int f = 0; f < 5; ++f)
            nxt[f] = v ? h2f2(base[f][po]) : 0;

        u64 c[5];
#pragma unroll
        for (int f = 0; f < 5; ++f) {
            u64 y = mul2(G0p, win[f][0]);
            y = fma2(G1p, win[f][1], y);
            y = fma2(G2p, win[f][2], y);
            y = fma2(G3p, win[f][3], y);
            y = fma2(G2p, win[f][4], y);
            y = fma2(G1p, win[f][5], y);
            y = fma2(G0p, win[f][6], y);
            c[f] = y;
        }

        float bh = bfac(h);
        u64 W2  = mul2(wwp, pk(bh, bh));
        u64 mu1 = fma2(W2, K05, c[0]);
        u64 mu2 = fma2(W2, K05, c[1]);
        u64 Ep2 = fma2(W2, Kn025, add2(c[2], mu1));
        u64 Et2 = fma2(W2, Kn025, add2(c[3], mu2));
        u64 Ept = fma2(add2(mu1, mu2), K05, fma2(W2, Kn025, c[4]));
        u64 mu1s = mul2(mu1, mu1), mu2s = mul2(mu2, mu2), mu12 = mul2(mu1, mu2);
        u64 s1  = fma2(mu1s, Kn1, Ep2);
        u64 s2  = fma2(mu2s, Kn1, Et2);
        u64 s12 = fma2(mu12, Kn1, Ept);
        u64 num = mul2(fma2(mu12, K2, KC1), fma2(s12, K2, KC2));
        u64 den = mul2(add2(add2(mu1s, mu2s), KC1), add2(add2(s1, s2), KC2));
        float2 nf = upk(num), df = upk(den);
        acc_ssim += __fdividef(nf.x, df.x) + __fdividef(nf.y, df.y);

#pragma unroll
        for (int f = 0; f < 5; ++f) {
#pragma unroll
            for (int k = 0; k < 6; ++k) win[f][k] = win[f][k + 1];
            win[f][6] = nxt[f];
        }
        po += 80;
    }

    __shared__ float sred[256];
    __shared__ bool is_last;
    int lt = threadIdx.x;
    sred[lt] = acc_ssim;
    __syncthreads();
    for (int s = 128; s > 0; s >>= 1) {
        if (lt < s) sred[lt] += sred[lt + s];
        __syncthreads();
    }
    if (lt == 0) {
        g_partials[blockIdx.x] = sred[0];
        __threadfence();
        int v = atomicAdd(&g_ctr, 1);
        is_last = (v == (int)gridDim.x - 1);
    }
    __syncthreads();

    if (is_last) {
        // deterministic fixed-order final reduction over 500 partials
        __shared__ double sm[256];
        double acc = 0.0;
        for (int i = lt; i < NPART; i += 256) acc += (double)g_partials[i];
        sm[lt] = acc;
        __syncthreads();
        for (int s = 128; s > 0; s >>= 1) {
            if (lt < s) sm[lt] += sm[lt + s];
            __syncthreads();
        }
        if (lt == 0) {
            out[0] = 1.f - (float)(sm[0] / (double)NVOX);
            g_ctr = 0;   // reset for next graph replay
        }
    }
}

extern "C" void kernel_launch(void* const* d_in, const int* in_sizes, int n_in,
                              void* d_out, int out_size) {
    const float* p = (const float*)d_in[0];
    const float* t = (const float*)d_in[1];
    float* out = (float*)d_out;

    passWD<<<(NWD + 255) / 256, 256>>>(p, t);   // 400 blocks, 102,400 threads
    passH<<<NPART, 256>>>(out);                 // 500 blocks, 128,000 threads
}

// round 9
// speedup vs baseline: 1.4216x; 1.4216x over previous
#include <cuda_runtime.h>
#include <cuda_fp16.h>

#define DD 160
#define HH 160
#define WW 160
#define NB 2
#define HW_ (HH * WW)
#define HW2 (HW_ / 2)
#define DHW_ (DD * HH * WW)          // 4,096,000
#define DHW2 (DHW_ / 2)
#define NVOX (NB * DHW_)             // 8,192,000
#define DCH 4
#define DL  (DD / DCH)               // 40
#define HCH 5
#define HL  (HH / HCH)               // 32
#define NPART 500                    // passH blocks

#define G0c 0.0125602f
#define G1c 0.0788279f
#define G2c 0.2372961f
#define G3c 0.3426315f

typedef unsigned long long u64;

__device__ __forceinline__ float gk(int k) {
    constexpr float g[7] = {G0c, G1c, G2c, G3c, G2c, G1c, G0c};
    return g[k];
}
__device__ __forceinline__ u64 pk(float lo, float hi) {
    u64 r; asm("mov.b64 %0, {%1, %2};" : "=l"(r) : "f"(lo), "f"(hi)); return r;
}
__device__ __forceinline__ float2 upk(u64 v) {
    float2 r; asm("mov.b64 {%0, %1}, %2;" : "=f"(r.x), "=f"(r.y) : "l"(v)); return r;
}
__device__ __forceinline__ u64 fma2(u64 a, u64 b, u64 c) {
    u64 d; asm("fma.rn.f32x2 %0, %1, %2, %3;" : "=l"(d) : "l"(a), "l"(b), "l"(c)); return d;
}
__device__ __forceinline__ u64 mul2(u64 a, u64 b) {
    u64 d; asm("mul.rn.f32x2 %0, %1, %2;" : "=l"(d) : "l"(a), "l"(b)); return d;
}
__device__ __forceinline__ u64 add2(u64 a, u64 b) {
    u64 d; asm("add.rn.f32x2 %0, %1, %2;" : "=l"(d) : "l"(a), "l"(b)); return d;
}
__device__ __forceinline__ unsigned h2u(__half2 h) {
    return *reinterpret_cast<unsigned*>(&h);
}

// zero-padding valid-weight factor per axis
__device__ __forceinline__ float bfac(int i) {
    float f = 1.f;
    if (i < 3)   f -= (i == 2 ? G0c : (i == 1 ? (G0c + G1c) : (G0c + G1c + G2c)));
    if (i > 156) f -= (i == 157 ? G0c : (i == 158 ? (G0c + G1c) : (G0c + G1c + G2c)));
    return f;
}

// fp16 scratch: 5 shifted fields x 2 batches, two ping-pong buffers (164 MB)
__device__ __half g_buf[10u * DHW_];
__device__ __half g_buf2[10u * DHW_];
__device__ float g_partials[NPART];
__device__ int g_ctr;

// ---------------------------------------------------------------------------
// passW: 7-tap W-conv of the 5 shifted fields {q,r,q2,r2,qr}, q=p-1/2.
// Thread owns an 8-wide w-octet; 16-float neighborhood via 4+4 LDG.128;
// all in registers; one STG.128 (8 halves) per field. No smem.
// ---------------------------------------------------------------------------
__global__ void __launch_bounds__(256) passW(const float* __restrict__ p,
                                             const float* __restrict__ t) {
    int tid = blockIdx.x * blockDim.x + threadIdx.x;   // 1,024,000
    int oct = tid % 20;
    int rem = tid / 20;
    int h   = rem % HH;
    int rm2 = rem / HH;
    int d   = rm2 % DD;
    int n   = rm2 / DD;
    int w0  = oct * 8;

    long rb = (long)n * DHW_ + ((long)d * HH + h) * WW + w0;
    const float4* p4 = (const float4*)(p + rb - 4);
    const float4* t4 = (const float4*)(t + rb - 4);
    const float4 z4 = {0.f, 0.f, 0.f, 0.f};

    float4 a0 = (oct > 0)  ? p4[0] : z4;
    float4 a1 = p4[1];
    float4 a2 = p4[2];
    float4 a3 = (oct < 19) ? p4[3] : z4;
    float4 b0 = (oct > 0)  ? t4[0] : z4;
    float4 b1 = t4[1];
    float4 b2 = t4[2];
    float4 b3 = (oct < 19) ? t4[3] : z4;

    float q[16], r[16];
    q[0]=a0.x-0.5f; q[1]=a0.y-0.5f; q[2]=a0.z-0.5f; q[3]=a0.w-0.5f;
    q[4]=a1.x-0.5f; q[5]=a1.y-0.5f; q[6]=a1.z-0.5f; q[7]=a1.w-0.5f;
    q[8]=a2.x-0.5f; q[9]=a2.y-0.5f; q[10]=a2.z-0.5f; q[11]=a2.w-0.5f;
    q[12]=a3.x-0.5f; q[13]=a3.y-0.5f; q[14]=a3.z-0.5f; q[15]=a3.w-0.5f;
    r[0]=b0.x-0.5f; r[1]=b0.y-0.5f; r[2]=b0.z-0.5f; r[3]=b0.w-0.5f;
    r[4]=b1.x-0.5f; r[5]=b1.y-0.5f; r[6]=b1.z-0.5f; r[7]=b1.w-0.5f;
    r[8]=b2.x-0.5f; r[9]=b2.y-0.5f; r[10]=b2.z-0.5f; r[11]=b2.w-0.5f;
    r[12]=b3.x-0.5f; r[13]=b3.y-0.5f; r[14]=b3.z-0.5f; r[15]=b3.w-0.5f;

    // force out-of-range field taps to exactly 0 (-0.5 shift must not leak)
    if (oct == 0)  { q[0]=q[1]=q[2]=q[3]=0.f;     r[0]=r[1]=r[2]=r[3]=0.f; }
    if (oct == 19) { q[12]=q[13]=q[14]=q[15]=0.f; r[12]=r[13]=r[14]=r[15]=0.f; }

    float acc[5][8];
#pragma unroll
    for (int f = 0; f < 5; ++f)
#pragma unroll
        for (int j = 0; j < 8; ++j) acc[f][j] = 0.f;

#pragma unroll
    for (int k = 0; k < 7; ++k) {
#pragma unroll
        for (int j = 0; j < 8; ++j) {
            float qa = q[1 + j + k], ra = r[1 + j + k];
            float g = gk(k);
            acc[0][j] = fmaf(g, qa, acc[0][j]);
            acc[1][j] = fmaf(g, ra, acc[1][j]);
            acc[2][j] = fmaf(g * qa, qa, acc[2][j]);
            acc[3][j] = fmaf(g * ra, ra, acc[3][j]);
            acc[4][j] = fmaf(g * qa, ra, acc[4][j]);
        }
    }

    long ob = rb / 8;   // uint4 index
    uint4* outv = (uint4*)g_buf;
#pragma unroll
    for (int f = 0; f < 5; ++f) {
        uint4 v;
        v.x = h2u(__floats2half2_rn(acc[f][0], acc[f][1]));
        v.y = h2u(__floats2half2_rn(acc[f][2], acc[f][3]));
        v.z = h2u(__floats2half2_rn(acc[f][4], acc[f][5]));
        v.w = h2u(__floats2half2_rn(acc[f][6], acc[f][7]));
        outv[(long)(f * NB) * (DHW_ / 8) + ob] = v;
    }
}

// ---------------------------------------------------------------------------
// passD: streaming 7-tap D-conv in HFMA2, 4 voxels (uint2 = 2 half2) per
// thread-step. Rolling 2x7 half2 window. g_buf -> g_buf2. No smem.
// ---------------------------------------------------------------------------
__global__ void __launch_bounds__(256) passD() {
    int tid = blockIdx.x * blockDim.x + threadIdx.x;   // 256,000
    int wq  = tid % 40;              // uint2 lane in row
    int rem = tid / 40;
    int ci  = rem % DCH;
    int rm2 = rem / DCH;
    int h   = rm2 % HH;
    int vol = rm2 / HH;
    int d0  = ci * DL;

    const uint2* src = (const uint2*)g_buf  + (long)vol * (DHW_ / 4) + (long)h * 40 + wq;
    uint2*       dst = (uint2*)g_buf2       + (long)vol * (DHW_ / 4) + (long)h * 40 + wq;
    const int DS = HW_ / 4;   // 6400 uint2 per d

    const __half2 Z = __float2half2_rn(0.f);
    const __half2 G0h = __float2half2_rn(G0c), G1h = __float2half2_rn(G1c);
    const __half2 G2h = __float2half2_rn(G2c), G3h = __float2half2_rn(G3c);

    __half2 wa[7], wb[7];
#pragma unroll
    for (int k = 0; k < 7; ++k) {
        int dd = d0 - 3 + k;
        if (dd >= 0 && dd < DD) {
            uint2 v = src[(long)dd * DS];
            wa[k] = *(__half2*)&v.x;
            wb[k] = *(__half2*)&v.y;
        } else { wa[k] = Z; wb[k] = Z; }
    }

    const uint2* sp = src + (long)(d0 + 4) * DS;
    uint2*       dp = dst + (long)d0 * DS;

#pragma unroll 4
    for (int i = 0; i < DL; ++i) {
        int dn = d0 + i + 4;
        __half2 na = Z, nb = Z;
        if (dn < DD) {
            uint2 v = *sp;
            na = *(__half2*)&v.x;
            nb = *(__half2*)&v.y;
        }
        __half2 ya = __hmul2(G0h, wa[0]);
        ya = __hfma2(G1h, wa[1], ya); ya = __hfma2(G2h, wa[2], ya);
        ya = __hfma2(G3h, wa[3], ya); ya = __hfma2(G2h, wa[4], ya);
        ya = __hfma2(G1h, wa[5], ya); ya = __hfma2(G0h, wa[6], ya);
        __half2 yb = __hmul2(G0h, wb[0]);
        yb = __hfma2(G1h, wb[1], yb); yb = __hfma2(G2h, wb[2], yb);
        yb = __hfma2(G3h, wb[3], yb); yb = __hfma2(G2h, wb[4], yb);
        yb = __hfma2(G1h, wb[5], yb); yb = __hfma2(G0h, wb[6], yb);
        uint2 o; o.x = h2u(ya); o.y = h2u(yb);
        *dp = o;
#pragma unroll
        for (int k = 0; k < 6; ++k) { wa[k] = wa[k + 1]; wb[k] = wb[k + 1]; }
        wa[6] = na; wb[6] = nb;
        sp += DS; dp += DS;
    }
}

// ---------------------------------------------------------------------------
// passH: streaming 7-tap H-conv (HFMA2 on half2 windows) + exact border
// reconstruction + SSIM (f32x2) + block reduction + last-block final reduce.
// Thread = (n, d, w-pair, h-chunk of 32).
// ---------------------------------------------------------------------------
__global__ void __launch_bounds__(256) passH(float* __restrict__ out) {
    int tid = blockIdx.x * blockDim.x + threadIdx.x;   // 128,000 exactly
    int wp  = tid % 80;
    int rem = tid / 80;
    int ci  = rem % HCH;
    int rm2 = rem / HCH;
    int d   = rm2 % DD;
    int n   = rm2 / DD;
    int h0  = ci * HL;
    int w2  = 2 * wp;

    const __half2 Z = __float2half2_rn(0.f);
    const __half2 G0h = __float2half2_rn(G0c), G1h = __float2half2_rn(G1c);
    const __half2 G2h = __float2half2_rn(G2c), G3h = __float2half2_rn(G3c);
    const u64 K05 = pk(0.5f,0.5f), Kn025 = pk(-0.25f,-0.25f), K2 = pk(2.f,2.f);
    const u64 KC1 = pk(1e-4f,1e-4f), KC2 = pk(9e-4f,9e-4f), Kn1 = pk(-1.f,-1.f);

    float bd = bfac(d);
    u64 wwp = pk(bd * bfac(w2), bd * bfac(w2 + 1));

    const __half2* base[5];
#pragma unroll
    for (int f = 0; f < 5; ++f)
        base[f] = (const __half2*)g_buf2 + (long)(f * NB + n) * DHW2 +
                  (long)d * HW2 + wp;

    __half2 win[5][7];
#pragma unroll
    for (int k = 0; k < 7; ++k) {
        int row = h0 - 3 + k;
        bool v = (row >= 0) && (row < HH);
        int ro = (v ? row : 0) * 80;
#pragma unroll
        for (int f = 0; f < 5; ++f)
            win[f][k] = v ? base[f][ro] : Z;
    }

    float acc_ssim = 0.f;
    int po = (h0 + 4) * 80;

#pragma unroll 4
    for (int i = 0; i < HL; ++i) {
        int h = h0 + i;
        bool v = (h + 4 < HH);
        __half2 nxt[5];
#pragma unroll
        for (int f = 0; f < 5; ++f)
            nxt[f] = v ? base[f][po] : Z;

        u64 c[5];
#pragma unroll
        for (int f = 0; f < 5; ++f) {
            __half2 y = __hmul2(G0h, win[f][0]);
            y = __hfma2(G1h, win[f][1], y);
            y = __hfma2(G2h, win[f][2], y);
            y = __hfma2(G3h, win[f][3], y);
            y = __hfma2(G2h, win[f][4], y);
            y = __hfma2(G1h, win[f][5], y);
            y = __hfma2(G0h, win[f][6], y);
            float2 cf = __half22float2(y);
            c[f] = pk(cf.x, cf.y);
        }

        float bh = bfac(h);
        u64 W2  = mul2(wwp, pk(bh, bh));
        u64 mu1 = fma2(W2, K05, c[0]);
        u64 mu2 = fma2(W2, K05, c[1]);
        u64 Ep2 = fma2(W2, Kn025, add2(c[2], mu1));
        u64 Et2 = fma2(W2, Kn025, add2(c[3], mu2));
        u64 Ept = fma2(add2(mu1, mu2), K05, fma2(W2, Kn025, c[4]));
        u64 mu1s = mul2(mu1, mu1), mu2s = mul2(mu2, mu2), mu12 = mul2(mu1, mu2);
        u64 s1  = fma2(mu1s, Kn1, Ep2);
        u64 s2  = fma2(mu2s, Kn1, Et2);
        u64 s12 = fma2(mu12, Kn1, Ept);
        u64 num = mul2(fma2(mu12, K2, KC1), fma2(s12, K2, KC2));
        u64 den = mul2(add2(add2(mu1s, mu2s), KC1), add2(add2(s1, s2), KC2));
        float2 nf = upk(num), df = upk(den);
        acc_ssim += __fdividef(nf.x, df.x) + __fdividef(nf.y, df.y);

#pragma unroll
        for (int f = 0; f < 5; ++f) {
#pragma unroll
            for (int k = 0; k < 6; ++k) win[f][k] = win[f][k + 1];
            win[f][6] = nxt[f];
        }
        po += 80;
    }

    __shared__ float sred[256];
    __shared__ bool is_last;
    int lt = threadIdx.x;
    sred[lt] = acc_ssim;
    __syncthreads();
    for (int s = 128; s > 0; s >>= 1) {
        if (lt < s) sred[lt] += sred[lt + s];
        __syncthreads();
    }
    if (lt == 0) {
        g_partials[blockIdx.x] = sred[0];
        __threadfence();
        int v = atomicAdd(&g_ctr, 1);
        is_last = (v == (int)gridDim.x - 1);
    }
    __syncthreads();

    if (is_last) {
        __shared__ double sm[256];
        double acc = 0.0;
        for (int i = lt; i < NPART; i += 256) acc += (double)g_partials[i];
        sm[lt] = acc;
        __syncthreads();
        for (int s = 128; s > 0; s >>= 1) {
            if (lt < s) sm[lt] += sm[lt + s];
            __syncthreads();
        }
        if (lt == 0) {
            out[0] = 1.f - (float)(sm[0] / (double)NVOX);
            g_ctr = 0;   // reset for next graph replay
        }
    }
}

extern "C" void kernel_launch(void* const* d_in, const int* in_sizes, int n_in,
                              void* d_out, int out_size) {
    const float* p = (const float*)d_in[0];
    const float* t = (const float*)d_in[1];
    float* out = (float*)d_out;

    passW<<<4000, 256>>>(p, t);     // 1,024,000 threads
    passD<<<1000, 256>>>();         //   256,000 threads (4 voxels/step)
    passH<<<NPART, 256>>>(out);     //   128,000 threads + folded reduce
}